// round 1
// baseline (speedup 1.0000x reference)
#include <cuda_runtime.h>

// Problem constants (fixed by the dataset)
constexpr int N_NODES = 50000;
constexpr int K_NBR   = 32;
constexpr int F_IN    = 64;
constexpr int F_OUT   = 64;
constexpr int BM      = 128;   // nodes per block tile

// Scratch: 1/dist per (node, neighbor). 6.4 MB device-global (no alloc allowed).
__device__ float g_inv[N_NODES * K_NBR];

// ---------------------------------------------------------------------------
// Kernel 1: inverse distance. dist = 0.5 when sq==0 (ref semantics) -> inv=2.
// ---------------------------------------------------------------------------
__global__ __launch_bounds__(256) void invdist_kernel(
    const float* __restrict__ pos, const int* __restrict__ nidx)
{
    int t = blockIdx.x * blockDim.x + threadIdx.x;
    if (t >= N_NODES * K_NBR) return;
    int i = t / K_NBR;
    int j = nidx[t];
    float dx = pos[i * 3 + 0] - pos[j * 3 + 0];
    float dy = pos[i * 3 + 1] - pos[j * 3 + 1];
    float dz = pos[i * 3 + 2] - pos[j * 3 + 2];
    float sq = fmaf(dx, dx, fmaf(dy, dy, dz * dz));
    g_inv[t] = (sq == 0.0f) ? 2.0f : rsqrtf(sq);
}

// ---------------------------------------------------------------------------
// Kernel 2: fused gather-scale-GEMM.
//   out[i, o] = leaky( sum_{k,f} h[nbr[i,k], f] * inv[i,k] * W[k*64+f, o] + b[o] )
// Block tile: BM=128 nodes x F_OUT=64 outputs. Loop over 32 neighbors,
// each neighbor contributes a 64-deep K-chunk.
// Threads: 256. Each thread owns an 8x4 accumulator micro-tile.
// ---------------------------------------------------------------------------
__global__ __launch_bounds__(256) void gnn_gemm_kernel(
    const float* __restrict__ h, const int* __restrict__ nidx,
    const float* __restrict__ W, const float* __restrict__ bias,
    float* __restrict__ out)
{
    __shared__ float As[BM * F_IN];      // 32 KB  [node_row][f]
    __shared__ float Bs[F_IN * F_OUT];   // 16 KB  [f][o]

    const int tid   = threadIdx.x;
    const int node0 = blockIdx.x * BM;

    // A-tile loading: 2 threads per node row, 32 floats (8 float4) each
    const int arow = tid >> 1;
    const int aseg = (tid & 1) * 32;
    // B-tile loading: 4 threads per weight row, 16 floats (4 float4) each
    const int brow = tid >> 2;
    const int bcol = (tid & 3) * 16;
    // C micro-tile: rows crow..crow+7, cols ccol..ccol+3
    const int crow = (tid >> 4) * 8;
    const int ccol = (tid & 15) * 4;

    const int  grow_a  = node0 + arow;
    const bool arow_ok = (grow_a < N_NODES);

    float acc[8][4];
#pragma unroll
    for (int i = 0; i < 8; ++i)
#pragma unroll
        for (int j = 0; j < 4; ++j) acc[i][j] = 0.0f;

    for (int k = 0; k < K_NBR; ++k) {
        // Per-row gather metadata straight from global (L2 hit, no smem stage)
        int   nbr = 0;
        float inv = 0.0f;
        if (arow_ok) {
            nbr = nidx[grow_a * K_NBR + k];
            inv = g_inv[grow_a * K_NBR + k];
        }
        const float4* asrc = (const float4*)(h + (size_t)nbr * F_IN + aseg);
        const float4* bsrc = (const float4*)(W + ((size_t)k * F_IN + brow) * F_OUT + bcol);

        __syncthreads();   // previous iteration's compute done reading smem

        float4* adst = (float4*)(As + arow * F_IN + aseg);
#pragma unroll
        for (int j = 0; j < 8; ++j) {
            float4 v = asrc[j];
            v.x *= inv; v.y *= inv; v.z *= inv; v.w *= inv;
            adst[j] = v;
        }
        float4* bdst = (float4*)(Bs + brow * F_OUT + bcol);
#pragma unroll
        for (int j = 0; j < 4; ++j) bdst[j] = bsrc[j];

        __syncthreads();   // tiles ready

        // 64-deep K-chunk, processed 4 at a time with float4 smem reads
#pragma unroll 4
        for (int kk4 = 0; kk4 < F_IN / 4; ++kk4) {
            float bfr[4][4];   // [kk_sub][col]
            *(float4*)bfr[0] = *(const float4*)(Bs + (kk4 * 4 + 0) * F_OUT + ccol);
            *(float4*)bfr[1] = *(const float4*)(Bs + (kk4 * 4 + 1) * F_OUT + ccol);
            *(float4*)bfr[2] = *(const float4*)(Bs + (kk4 * 4 + 2) * F_OUT + ccol);
            *(float4*)bfr[3] = *(const float4*)(Bs + (kk4 * 4 + 3) * F_OUT + ccol);
#pragma unroll
            for (int i = 0; i < 8; ++i) {
                float afr[4];
                *(float4*)afr = *(const float4*)(As + (crow + i) * F_IN + kk4 * 4);
#pragma unroll
                for (int t = 0; t < 4; ++t)
#pragma unroll
                    for (int j = 0; j < 4; ++j)
                        acc[i][j] = fmaf(afr[t], bfr[t][j], acc[i][j]);
            }
        }
    }

    // Epilogue: bias + leaky_relu(0.01), vectorized store
    float4 bv = *(const float4*)(bias + ccol);
#pragma unroll
    for (int i = 0; i < 8; ++i) {
        int grow = node0 + crow + i;
        if (grow < N_NODES) {
            float4 r;
            r.x = acc[i][0] + bv.x;
            r.y = acc[i][1] + bv.y;
            r.z = acc[i][2] + bv.z;
            r.w = acc[i][3] + bv.w;
            r.x = (r.x > 0.0f) ? r.x : 0.01f * r.x;
            r.y = (r.y > 0.0f) ? r.y : 0.01f * r.y;
            r.z = (r.z > 0.0f) ? r.z : 0.01f * r.z;
            r.w = (r.w > 0.0f) ? r.w : 0.01f * r.w;
            *(float4*)(out + (size_t)grow * F_OUT + ccol) = r;
        }
    }
}

// ---------------------------------------------------------------------------
// Harness entry. Inputs (metadata order): h, pos, neighbor_idx, weight, bias_p
// ---------------------------------------------------------------------------
extern "C" void kernel_launch(void* const* d_in, const int* in_sizes, int n_in,
                              void* d_out, int out_size)
{
    const float* h    = (const float*)d_in[0];
    const float* pos  = (const float*)d_in[1];
    const int*   nidx = (const int*)d_in[2];
    const float* W    = (const float*)d_in[3];
    const float* bias = (const float*)d_in[4];
    float*       out  = (float*)d_out;

    invdist_kernel<<<(N_NODES * K_NBR + 255) / 256, 256>>>(pos, nidx);
    gnn_gemm_kernel<<<(N_NODES + BM - 1) / BM, 256>>>(h, nidx, W, bias, out);
}

// round 6
// speedup vs baseline: 1.4287x; 1.4287x over previous
#include <cuda_runtime.h>
#include <cstdint>

// Problem constants (fixed by the dataset)
constexpr int N_NODES = 50000;
constexpr int K_NBR   = 32;
constexpr int F_IN    = 64;
constexpr int F_OUT   = 64;
constexpr int BM      = 128;   // nodes per block tile

// Scratch: 1/dist per (node, neighbor). 6.4 MB device-global (no alloc allowed).
__device__ float g_inv[N_NODES * K_NBR];

// ---------------------------------------------------------------------------
// Kernel 1: inverse distance. dist = 0.5 when sq==0 (ref semantics) -> inv=2.
// ---------------------------------------------------------------------------
__global__ __launch_bounds__(256) void invdist_kernel(
    const float* __restrict__ pos, const int* __restrict__ nidx)
{
    int t = blockIdx.x * blockDim.x + threadIdx.x;
    if (t >= N_NODES * K_NBR) return;
    int i = t / K_NBR;
    int j = nidx[t];
    float dx = pos[i * 3 + 0] - pos[j * 3 + 0];
    float dy = pos[i * 3 + 1] - pos[j * 3 + 1];
    float dz = pos[i * 3 + 2] - pos[j * 3 + 2];
    float sq = fmaf(dx, dx, fmaf(dy, dy, dz * dz));
    g_inv[t] = (sq == 0.0f) ? 2.0f : rsqrtf(sq);
}

// Packed fp32x2 helpers (Blackwell sm_103a)
#define FMA2(d, a, b) \
    asm("fma.rn.f32x2 %0, %1, %2, %3;" : "=l"(d) : "l"(a), "l"(b), "l"(d))
#define PACK_DUP(d, s) \
    asm("mov.b64 %0, {%1, %1};" : "=l"(d) : "r"(s))
#define UNPACK2(lo, hi, s) \
    asm("mov.b64 {%0, %1}, %2;" : "=f"(lo), "=f"(hi) : "l"(s))

// ---------------------------------------------------------------------------
// Kernel 2: fused gather-scale-GEMM with f32x2 packed FMA.
// Block tile: 128 nodes x 64 outputs, 128 threads.
// Microtile per thread: 8 rows x 8 cols, cols held as 4 (o, o+32) pairs.
// A tile is XOR-swizzled (float4 index j stored at j ^ (row & 7)) so both the
// gather-stage STS.128 and the compute LDS.128 are bank-conflict-free.
// B tile is staged as float2 pairs Bs2[k][p] = (W[k][p], W[k][p+32]) so the
// f32x2 B operand is a single conflict-free LDS.64.
// ---------------------------------------------------------------------------
__global__ __launch_bounds__(128, 3) void gnn_gemm_kernel(
    const float* __restrict__ h, const int* __restrict__ nidx,
    const float* __restrict__ W, const float* __restrict__ bias,
    float* __restrict__ out)
{
    __shared__ float4 As4[BM * 16];      // 32 KB, swizzled [row][j^ (row&7)]
    __shared__ float2 Bs2[F_IN * 32];    // 16 KB, [k][pair p] = (col p, col p+32)

    const int tid   = threadIdx.x;
    const int node0 = blockIdx.x * BM;
    const int cg    = tid & 7;           // col group: pairs {cg, cg+8, cg+16, cg+24}
    const int crow  = (tid >> 3) * 8;    // first of 8 rows

    const int  grow_s  = node0 + tid;    // staging row (1 thread per row)
    const bool srow_ok = (grow_s < N_NODES);
    const int  sw      = tid & 7;        // staging swizzle

    unsigned long long acc[8][4];
#pragma unroll
    for (int i = 0; i < 8; ++i)
#pragma unroll
        for (int m = 0; m < 4; ++m) acc[i][m] = 0ULL;

    for (int k = 0; k < K_NBR; ++k) {
        int   nbr = 0;
        float inv = 0.0f;
        if (srow_ok) {
            nbr = nidx[grow_s * K_NBR + k];
            inv = g_inv[grow_s * K_NBR + k];
        }
        const float4* hsrc = (const float4*)(h + (size_t)nbr * F_IN);
        const float*  wk   = W + (size_t)k * F_IN * F_OUT;

        __syncthreads();   // previous iteration done reading smem

        // A stage: 16 float4 per row, scaled by inv, XOR-swizzled
#pragma unroll
        for (int j = 0; j < 16; ++j) {
            float4 v = hsrc[j];
            v.x *= inv; v.y *= inv; v.z *= inv; v.w *= inv;
            As4[tid * 16 + (j ^ sw)] = v;
        }
        // B stage: build (o, o+32) pairs; 16 float2 per thread, coalesced reads
#pragma unroll
        for (int m = 0; m < 16; ++m) {
            int idx = tid + m * 128;
            int f   = idx >> 5;          // k-position within chunk (0..63)
            int p   = idx & 31;          // pair index
            Bs2[f * 32 + p] = make_float2(wk[f * 64 + p], wk[f * 64 + p + 32]);
        }

        __syncthreads();   // tiles ready

#pragma unroll 4
        for (int kk4 = 0; kk4 < 16; ++kk4) {
            // A fragment: 8 rows x 4 k-values (row i's swizzle constant is i)
            uint4 a[8];
#pragma unroll
            for (int i = 0; i < 8; ++i)
                a[i] = *(const uint4*)&As4[(crow + i) * 16 + (kk4 ^ i)];

#pragma unroll
            for (int ks = 0; ks < 4; ++ks) {
                const int kidx = kk4 * 4 + ks;
                unsigned long long b[4];
#pragma unroll
                for (int m = 0; m < 4; ++m)
                    b[m] = *(const unsigned long long*)&Bs2[kidx * 32 + cg + 8 * m];
#pragma unroll
                for (int i = 0; i < 8; ++i) {
                    uint32_t as = (ks == 0) ? a[i].x : (ks == 1) ? a[i].y
                                : (ks == 2) ? a[i].z : a[i].w;
                    unsigned long long ap;
                    PACK_DUP(ap, as);
                    FMA2(acc[i][0], ap, b[0]);
                    FMA2(acc[i][1], ap, b[1]);
                    FMA2(acc[i][2], ap, b[2]);
                    FMA2(acc[i][3], ap, b[3]);
                }
            }
        }
    }

    // Epilogue: bias + leaky_relu(0.01)
    float bl[4], bh[4];
#pragma unroll
    for (int m = 0; m < 4; ++m) {
        bl[m] = bias[cg + 8 * m];
        bh[m] = bias[cg + 8 * m + 32];
    }
#pragma unroll
    for (int i = 0; i < 8; ++i) {
        int grow = node0 + crow + i;
        if (grow < N_NODES) {
            float* orow = out + (size_t)grow * F_OUT;
#pragma unroll
            for (int m = 0; m < 4; ++m) {
                float lo, hi;
                UNPACK2(lo, hi, acc[i][m]);
                lo += bl[m];
                hi += bh[m];
                lo = (lo > 0.0f) ? lo : 0.01f * lo;
                hi = (hi > 0.0f) ? hi : 0.01f * hi;
                orow[cg + 8 * m]      = lo;
                orow[cg + 8 * m + 32] = hi;
            }
        }
    }
}

// ---------------------------------------------------------------------------
// Harness entry. Inputs (metadata order): h, pos, neighbor_idx, weight, bias_p
// ---------------------------------------------------------------------------
extern "C" void kernel_launch(void* const* d_in, const int* in_sizes, int n_in,
                              void* d_out, int out_size)
{
    const float* h    = (const float*)d_in[0];
    const float* pos  = (const float*)d_in[1];
    const int*   nidx = (const int*)d_in[2];
    const float* W    = (const float*)d_in[3];
    const float* bias = (const float*)d_in[4];
    float*       out  = (float*)d_out;

    invdist_kernel<<<(N_NODES * K_NBR + 255) / 256, 256>>>(pos, nidx);
    gnn_gemm_kernel<<<(N_NODES + BM - 1) / BM, 128>>>(h, nidx, W, bias, out);
}

// round 8
// speedup vs baseline: 1.8562x; 1.2992x over previous
#include <cuda_runtime.h>
#include <cuda_bf16.h>
#include <cstdint>

// ---------------------------------------------------------------------------
// Problem constants
// ---------------------------------------------------------------------------
constexpr int N_NODES = 50000;
constexpr int K_NBR   = 32;
constexpr int F_IN    = 64;
constexpr int F_OUT   = 64;
constexpr int BM      = 128;                       // nodes per CTA tile
constexpr int NBLK    = (N_NODES + BM - 1) / BM;   // 391

// Padded row stride for smem tiles: 72 bf16 = 144 B.
// 8 consecutive rows -> byte offsets r*144 mod 128 = r*16 -> distinct 16B banks
// => conflict-free ldmatrix and STS.128.
constexpr int RS   = 72;                  // elements
constexpr int RSB  = RS * 2;              // bytes = 144
constexpr int A_TILE = BM * RSB;          // 18432 B per term
constexpr int B_TILE = F_IN * RSB;        // 9216 B per term

// Dynamic smem layout
constexpr int SM_AHI = 0;
constexpr int SM_ALO = SM_AHI + A_TILE;   // 18432
constexpr int SM_BHI = SM_ALO + A_TILE;   // 36864
constexpr int SM_BLO = SM_BHI + B_TILE;   // 46080
constexpr int SMEM_BYTES = SM_BLO + B_TILE;   // 55296

// ---------------------------------------------------------------------------
// Device scratch (allocation is forbidden -> device globals)
// ---------------------------------------------------------------------------
__device__ float g_inv[N_NODES * K_NBR];
// Pre-split, transposed, padded W tiles: [nbr][k=0..63][n=0..71(pad)] bf16
__device__ uint4 g_Bhi4[K_NBR * (B_TILE / 16)];
__device__ uint4 g_Blo4[K_NBR * (B_TILE / 16)];

// ---------------------------------------------------------------------------
// PTX helpers (all baseline PTX, valid at target sm_103)
// ---------------------------------------------------------------------------
__device__ __forceinline__ uint32_t smem_u32(const void* p) {
    uint32_t a;
    asm("{ .reg .u64 t; cvta.to.shared.u64 t, %1; cvt.u32.u64 %0, t; }"
        : "=r"(a) : "l"(p));
    return a;
}
#define LDM_X4(r, addr) \
    asm volatile("ldmatrix.sync.aligned.m8n8.x4.shared.b16 {%0,%1,%2,%3}, [%4];" \
        : "=r"((r)[0]), "=r"((r)[1]), "=r"((r)[2]), "=r"((r)[3]) : "r"(addr))
#define LDM_X4T(r, addr) \
    asm volatile("ldmatrix.sync.aligned.m8n8.x4.trans.shared.b16 {%0,%1,%2,%3}, [%4];" \
        : "=r"((r)[0]), "=r"((r)[1]), "=r"((r)[2]), "=r"((r)[3]) : "r"(addr))
#define MMA16816(d, a, b0, b1) \
    asm volatile("mma.sync.aligned.m16n8k16.row.col.f32.bf16.bf16.f32 " \
        "{%0,%1,%2,%3}, {%4,%5,%6,%7}, {%8,%9}, {%0,%1,%2,%3};" \
        : "+f"((d)[0]), "+f"((d)[1]), "+f"((d)[2]), "+f"((d)[3]) \
        : "r"((a)[0]), "r"((a)[1]), "r"((a)[2]), "r"((a)[3]), "r"(b0), "r"(b1))

// ---------------------------------------------------------------------------
// Kernel 1: inverse distance. dist = 0.5 when sq==0 -> inv = 2.
// ---------------------------------------------------------------------------
__global__ __launch_bounds__(256) void invdist_kernel(
    const float* __restrict__ pos, const int* __restrict__ nidx)
{
    int t = blockIdx.x * blockDim.x + threadIdx.x;
    if (t >= N_NODES * K_NBR) return;
    int i = t / K_NBR;
    int j = nidx[t];
    float dx = pos[i * 3 + 0] - pos[j * 3 + 0];
    float dy = pos[i * 3 + 1] - pos[j * 3 + 1];
    float dz = pos[i * 3 + 2] - pos[j * 3 + 2];
    float sq = fmaf(dx, dx, fmaf(dy, dy, dz * dz));
    g_inv[t] = (sq == 0.0f) ? 2.0f : rsqrtf(sq);
}

// ---------------------------------------------------------------------------
// Kernel 2: split W into bf16 hi/lo, transposed to B[nbr][k][n], padded rows.
// Padding columns (n=64..71) stay zero (device globals are zero-initialized
// and never written) and are never read by ldmatrix.
// ---------------------------------------------------------------------------
__global__ __launch_bounds__(256) void convert_w_kernel(const float* __restrict__ W)
{
    int idx = blockIdx.x * blockDim.x + threadIdx.x;   // 32*64*64 = 131072
    if (idx >= K_NBR * F_IN * F_OUT) return;
    int nbr = idx >> 12;
    int kk  = (idx >> 6) & 63;
    int n   = idx & 63;
    float w = W[((size_t)nbr * F_IN + kk) * F_OUT + n];
    __nv_bfloat16 hi = __float2bfloat16_rn(w);
    __nv_bfloat16 lo = __float2bfloat16_rn(w - __bfloat162float(hi));
    size_t off = ((size_t)nbr * F_IN + kk) * RS + n;
    ((__nv_bfloat16*)g_Bhi4)[off] = hi;
    ((__nv_bfloat16*)g_Blo4)[off] = lo;
}

// ---------------------------------------------------------------------------
// Kernel 3: fused gather-scale-GEMM on mma.sync (split-bf16, fp32 acc).
// 256 threads = 8 warps; warp w owns rows [w*16, w*16+16) x all 64 cols.
// Per neighbor: stage A (gather/scale/split) + B (copy pre-split tiles),
// then 3-term mma: Ah*Bh + Ah*Bl + Al*Bh.
// ---------------------------------------------------------------------------
extern __shared__ uint8_t dynsmem[];

__global__ __launch_bounds__(256, 2) void gnn_mma_kernel(
    const float* __restrict__ h, const int* __restrict__ nidx,
    const float* __restrict__ bias, float* __restrict__ out)
{
    const int tid = threadIdx.x;
    const int wid = tid >> 5;
    const int lid = tid & 31;
    const int node0 = blockIdx.x * BM;

    const uint32_t sbase = smem_u32(dynsmem);

    // ldmatrix source addresses (per lane):
    //   A: lane l -> row (l&15) of warp tile, k-offset (l>>4)*8 elements
    //   B (.trans): lane l -> k-row (l&15), n-offset (l>>4)*8 elements
    const uint32_t lrow = (lid & 15);
    const uint32_t loff = (lid >> 4) * 16;          // 8 elements * 2B
    const uint32_t aHi = sbase + SM_AHI + (wid * 16 + lrow) * RSB + loff;
    const uint32_t aLo = aHi + (SM_ALO - SM_AHI);
    const uint32_t bHi = sbase + SM_BHI + lrow * RSB + loff;
    const uint32_t bLo = bHi + (SM_BLO - SM_BHI);

    // Staging roles: row r = tid>>1 (0..127), half hh = tid&1 (k 32*hh..)
    const int r  = tid >> 1;
    const int hh = tid & 1;
    const int grow_s = node0 + r;
    const bool srow_ok = (grow_s < N_NODES);

    uint8_t* AhiP = dynsmem + SM_AHI + r * RSB + hh * 64;
    uint8_t* AloP = dynsmem + SM_ALO + r * RSB + hh * 64;
    uint4*   BhiD = (uint4*)(dynsmem + SM_BHI);
    uint4*   BloD = (uint4*)(dynsmem + SM_BLO);

    float acc[8][4];
#pragma unroll
    for (int i = 0; i < 8; ++i)
#pragma unroll
        for (int j = 0; j < 4; ++j) acc[i][j] = 0.0f;

    for (int k = 0; k < K_NBR; ++k) {
        // ---- load globals (overlaps previous iteration's mma) ----
        int   nbr = 0;
        float inv = 0.0f;
        if (srow_ok) {
            nbr = nidx[grow_s * K_NBR + k];
            inv = g_inv[grow_s * K_NBR + k];
        }
        const float4* hsrc = (const float4*)(h + (size_t)nbr * F_IN + hh * 32);
        float4 hv[8];
#pragma unroll
        for (int j = 0; j < 8; ++j) hv[j] = hsrc[j];

        const uint4* sBh = g_Bhi4 + (size_t)k * (B_TILE / 16);
        const uint4* sBl = g_Blo4 + (size_t)k * (B_TILE / 16);
        uint4 bh0 = sBh[tid], bh1 = sBh[tid + 256];
        uint4 bl0 = sBl[tid], bl1 = sBl[tid + 256];
        uint4 bh2, bl2;
        if (tid < B_TILE / 16 - 512) { bh2 = sBh[tid + 512]; bl2 = sBl[tid + 512]; }

        __syncthreads();   // previous iteration done reading smem

        // ---- stage A: scale, split to bf16 hi/lo ----
        uint32_t hiw[16], low[16];
#pragma unroll
        for (int j = 0; j < 8; ++j) {
            float4 t4 = hv[j];
            float2 p0 = make_float2(t4.x * inv, t4.y * inv);
            float2 p1 = make_float2(t4.z * inv, t4.w * inv);
            __nv_bfloat162 h0 = __float22bfloat162_rn(p0);
            __nv_bfloat162 h1 = __float22bfloat162_rn(p1);
            uint32_t w0 = *(uint32_t*)&h0, w1 = *(uint32_t*)&h1;
            hiw[2 * j + 0] = w0;
            hiw[2 * j + 1] = w1;
            float2 r0 = make_float2(p0.x - __uint_as_float(w0 << 16),
                                    p0.y - __uint_as_float(w0 & 0xFFFF0000u));
            float2 r1 = make_float2(p1.x - __uint_as_float(w1 << 16),
                                    p1.y - __uint_as_float(w1 & 0xFFFF0000u));
            __nv_bfloat162 l0 = __float22bfloat162_rn(r0);
            __nv_bfloat162 l1 = __float22bfloat162_rn(r1);
            low[2 * j + 0] = *(uint32_t*)&l0;
            low[2 * j + 1] = *(uint32_t*)&l1;
        }
#pragma unroll
        for (int jj = 0; jj < 4; ++jj) {
            *(uint4*)(AhiP + jj * 16) = ((uint4*)hiw)[jj];
            *(uint4*)(AloP + jj * 16) = ((uint4*)low)[jj];
        }
        // ---- stage B ----
        BhiD[tid] = bh0;  BhiD[tid + 256] = bh1;
        BloD[tid] = bl0;  BloD[tid + 256] = bl1;
        if (tid < B_TILE / 16 - 512) { BhiD[tid + 512] = bh2; BloD[tid + 512] = bl2; }

        __syncthreads();   // tiles ready

        // ---- mma: 4 k16 chunks x 8 n-tiles x 3 terms ----
#pragma unroll
        for (int kc = 0; kc < 4; ++kc) {
            uint32_t ah[4], al[4];
            LDM_X4(ah, aHi + kc * 32);
            LDM_X4(al, aLo + kc * 32);
#pragma unroll
            for (int g2 = 0; g2 < 4; ++g2) {
                uint32_t bh[4], bl[4];
                LDM_X4T(bh, bHi + kc * 16 * RSB + g2 * 32);
                LDM_X4T(bl, bLo + kc * 16 * RSB + g2 * 32);
                MMA16816(acc[g2 * 2 + 0], ah, bh[0], bh[1]);
                MMA16816(acc[g2 * 2 + 0], ah, bl[0], bl[1]);
                MMA16816(acc[g2 * 2 + 0], al, bh[0], bh[1]);
                MMA16816(acc[g2 * 2 + 1], ah, bh[2], bh[3]);
                MMA16816(acc[g2 * 2 + 1], ah, bl[2], bl[3]);
                MMA16816(acc[g2 * 2 + 1], al, bh[2], bh[3]);
            }
        }
        __syncthreads();   // done reading smem before next staging
    }

    // ---- epilogue: bias + leaky_relu(0.01), direct register->global ----
    const int g  = lid >> 2;
    const int c0 = (lid & 3) * 2;
    const int row0 = node0 + wid * 16 + g;
    const int row1 = row0 + 8;
#pragma unroll
    for (int nt = 0; nt < 8; ++nt) {
        int col = nt * 8 + c0;
        float bx = bias[col], by = bias[col + 1];
        float2 v0 = make_float2(acc[nt][0] + bx, acc[nt][1] + by);
        float2 v1 = make_float2(acc[nt][2] + bx, acc[nt][3] + by);
        v0.x = (v0.x > 0.0f) ? v0.x : 0.01f * v0.x;
        v0.y = (v0.y > 0.0f) ? v0.y : 0.01f * v0.y;
        v1.x = (v1.x > 0.0f) ? v1.x : 0.01f * v1.x;
        v1.y = (v1.y > 0.0f) ? v1.y : 0.01f * v1.y;
        if (row0 < N_NODES) *(float2*)(out + (size_t)row0 * F_OUT + col) = v0;
        if (row1 < N_NODES) *(float2*)(out + (size_t)row1 * F_OUT + col) = v1;
    }
}

// ---------------------------------------------------------------------------
// Harness entry. Inputs: h, pos, neighbor_idx, weight, bias_p
// ---------------------------------------------------------------------------
extern "C" void kernel_launch(void* const* d_in, const int* in_sizes, int n_in,
                              void* d_out, int out_size)
{
    const float* h    = (const float*)d_in[0];
    const float* pos  = (const float*)d_in[1];
    const int*   nidx = (const int*)d_in[2];
    const float* W    = (const float*)d_in[3];
    const float* bias = (const float*)d_in[4];
    float*       out  = (float*)d_out;

    static bool attr_set = false;
    if (!attr_set) {
        cudaFuncSetAttribute(gnn_mma_kernel,
                             cudaFuncAttributeMaxDynamicSharedMemorySize, SMEM_BYTES);
        attr_set = true;
    }

    invdist_kernel<<<(N_NODES * K_NBR + 255) / 256, 256>>>(pos, nidx);
    convert_w_kernel<<<(K_NBR * F_IN * F_OUT + 255) / 256, 256>>>(W);
    gnn_mma_kernel<<<NBLK, 256, SMEM_BYTES>>>(h, nidx, bias, out);
}

// round 9
// speedup vs baseline: 3.2793x; 1.7666x over previous
#include <cuda_runtime.h>
#include <cuda_fp16.h>
#include <cstdint>

// ---------------------------------------------------------------------------
// Problem constants
// ---------------------------------------------------------------------------
constexpr int N_NODES = 50000;
constexpr int K_NBR   = 32;
constexpr int F_IN    = 64;
constexpr int F_OUT   = 64;
constexpr int BM      = 128;                       // nodes per CTA tile
constexpr int NBLK    = (N_NODES + BM - 1) / BM;   // 391

// Padded row stride: 72 fp16 = 144 B. Rows r=0..7 -> byte offset r*144 mod 128
// = r*16 -> distinct 16B banks => conflict-free ldmatrix and STS.128.
constexpr int RS   = 72;
constexpr int RSB  = RS * 2;              // 144 B
constexpr int A_TILE = BM * RSB;          // 18432 B
constexpr int B_TILE = F_IN * RSB;        //  9216 B
constexpr int BUFSZ  = A_TILE + B_TILE;   // 27648 B per buffer
constexpr int SMEM_BYTES = 2 * BUFSZ;     // 55296 B (double buffered)

// ---------------------------------------------------------------------------
// Device scratch: pre-converted fp16 W^T tiles [nbr][k=0..63][n=0..71(pad)]
// ---------------------------------------------------------------------------
__device__ uint4 g_Wh4[K_NBR * (B_TILE / 16)];

// ---------------------------------------------------------------------------
// PTX helpers (baseline PTX only — valid at virtual target sm_103)
// ---------------------------------------------------------------------------
__device__ __forceinline__ uint32_t smem_u32(const void* p) {
    uint32_t a;
    asm("{ .reg .u64 t; cvta.to.shared.u64 t, %1; cvt.u32.u64 %0, t; }"
        : "=r"(a) : "l"(p));
    return a;
}
#define LDM_X4(r, addr) \
    asm volatile("ldmatrix.sync.aligned.m8n8.x4.shared.b16 {%0,%1,%2,%3}, [%4];" \
        : "=r"((r)[0]), "=r"((r)[1]), "=r"((r)[2]), "=r"((r)[3]) : "r"(addr))
#define LDM_X4T(r, addr) \
    asm volatile("ldmatrix.sync.aligned.m8n8.x4.trans.shared.b16 {%0,%1,%2,%3}, [%4];" \
        : "=r"((r)[0]), "=r"((r)[1]), "=r"((r)[2]), "=r"((r)[3]) : "r"(addr))
#define MMA16816(d, a, b0, b1) \
    asm volatile("mma.sync.aligned.m16n8k16.row.col.f32.f16.f16.f32 " \
        "{%0,%1,%2,%3}, {%4,%5,%6,%7}, {%8,%9}, {%0,%1,%2,%3};" \
        : "+f"((d)[0]), "+f"((d)[1]), "+f"((d)[2]), "+f"((d)[3]) \
        : "r"((a)[0]), "r"((a)[1]), "r"((a)[2]), "r"((a)[3]), "r"(b0), "r"(b1))
#define CP_ASYNC16(dst, src) \
    asm volatile("cp.async.cg.shared.global [%0], [%1], 16;" \
        :: "r"(dst), "l"(src) : "memory")
#define CP_COMMIT()  asm volatile("cp.async.commit_group;" ::: "memory")
#define CP_WAIT0()   asm volatile("cp.async.wait_group 0;" ::: "memory")

// ---------------------------------------------------------------------------
// Kernel 1: convert W to fp16, transposed to [nbr][k][n], padded rows.
// Padding (n=64..71) stays zero (device globals zero-init) and is never read.
// ---------------------------------------------------------------------------
__global__ __launch_bounds__(256) void convert_w_kernel(const float* __restrict__ W)
{
    int idx = blockIdx.x * blockDim.x + threadIdx.x;   // 32*64*64 = 131072
    if (idx >= K_NBR * F_IN * F_OUT) return;
    int nbr = idx >> 12;
    int kk  = (idx >> 6) & 63;
    int n   = idx & 63;
    float w = W[((size_t)nbr * F_IN + kk) * F_OUT + n];
    ((__half*)g_Wh4)[((size_t)nbr * F_IN + kk) * RS + n] = __float2half_rn(w);
}

// ---------------------------------------------------------------------------
// Kernel 2: fused gather-scale-GEMM on mma.sync, single-term fp16, fp32 acc.
// 256 threads = 8 warps; warp w owns rows [w*16, w*16+16) x 64 cols.
// Double-buffered smem; per iteration: stage(k+1) -> buf^1 (A manual with
// inline inv-dist, B via cp.async), mma(k) on buf, one __syncthreads.
// ---------------------------------------------------------------------------
extern __shared__ uint8_t dynsmem[];

__global__ __launch_bounds__(256, 3) void gnn_mma_kernel(
    const float* __restrict__ h, const int* __restrict__ nidx,
    const float* __restrict__ pos, const float* __restrict__ bias,
    float* __restrict__ out)
{
    const int tid = threadIdx.x;
    const int wid = tid >> 5;
    const int lid = tid & 31;
    const int node0 = blockIdx.x * BM;

    const uint32_t sbase = smem_u32(dynsmem);
    const uint32_t lrow = (lid & 15);
    const uint32_t loff = (lid >> 4) * 16;

    // Staging roles: row r = tid>>1 (0..127), half hh = tid&1 (k 32*hh..)
    const int r  = tid >> 1;
    const int hh = tid & 1;
    const int grow = node0 + r;
    const bool ok = (grow < N_NODES);
    float pix = 0.f, piy = 0.f, piz = 0.f;
    if (ok) {
        pix = pos[(size_t)grow * 3 + 0];
        piy = pos[(size_t)grow * 3 + 1];
        piz = pos[(size_t)grow * 3 + 2];
    }
    const int* nrow = nidx + (size_t)grow * K_NBR;

    // A stage: gather h row, compute 1/dist inline, scale, fp16-convert, STS
    auto stageA = [&](int k, int buf) {
        int   nbr = 0;
        float inv = 0.0f;
        if (ok) {
            nbr = nrow[k];
            float dx = pix - pos[(size_t)nbr * 3 + 0];
            float dy = piy - pos[(size_t)nbr * 3 + 1];
            float dz = piz - pos[(size_t)nbr * 3 + 2];
            float sq = fmaf(dx, dx, fmaf(dy, dy, dz * dz));
            inv = (sq == 0.0f) ? 2.0f : rsqrtf(sq);   // dist==0 -> 0.5 -> inv 2
        }
        const float4* hsrc = (const float4*)(h + (size_t)nbr * F_IN + hh * 32);
        uint32_t w[16];
#pragma unroll
        for (int j = 0; j < 8; ++j) {
            float4 t4 = hsrc[j];
            __half2 p0 = __floats2half2_rn(t4.x * inv, t4.y * inv);
            __half2 p1 = __floats2half2_rn(t4.z * inv, t4.w * inv);
            w[2 * j + 0] = *(uint32_t*)&p0;
            w[2 * j + 1] = *(uint32_t*)&p1;
        }
        uint8_t* dst = dynsmem + buf * BUFSZ + r * RSB + hh * 64;
#pragma unroll
        for (int jj = 0; jj < 4; ++jj)
            *(uint4*)(dst + jj * 16) = ((uint4*)w)[jj];
    };
    // B stage: 576 uint4 via cp.async (L2-resident pre-converted tiles)
    auto stageB = [&](int k, int buf) {
        const uint4* src = g_Wh4 + (size_t)k * (B_TILE / 16);
        uint32_t dst = sbase + buf * BUFSZ + A_TILE;
        CP_ASYNC16(dst + tid * 16,         (const void*)(src + tid));
        CP_ASYNC16(dst + (tid + 256) * 16, (const void*)(src + tid + 256));
        if (tid < B_TILE / 16 - 512)
            CP_ASYNC16(dst + (tid + 512) * 16, (const void*)(src + tid + 512));
        CP_COMMIT();
    };

    // Prologue: stage k=0 into buf 0
    stageA(0, 0);
    stageB(0, 0);
    CP_WAIT0();
    __syncthreads();

    float acc[8][4];
#pragma unroll
    for (int i = 0; i < 8; ++i)
#pragma unroll
        for (int j = 0; j < 4; ++j) acc[i][j] = 0.0f;

    for (int k = 0; k < K_NBR; ++k) {
        const int buf = k & 1;
        if (k + 1 < K_NBR) {
            stageA(k + 1, buf ^ 1);
            stageB(k + 1, buf ^ 1);
        }

        const uint32_t aBase = sbase + buf * BUFSZ + (wid * 16 + lrow) * RSB + loff;
        const uint32_t bBase = sbase + buf * BUFSZ + A_TILE + lrow * RSB + loff;
#pragma unroll
        for (int kc = 0; kc < 4; ++kc) {
            uint32_t a[4];
            LDM_X4(a, aBase + kc * 32);
#pragma unroll
            for (int g2 = 0; g2 < 4; ++g2) {
                uint32_t b[4];
                LDM_X4T(b, bBase + kc * 16 * RSB + g2 * 32);
                MMA16816(acc[g2 * 2 + 0], a, b[0], b[1]);
                MMA16816(acc[g2 * 2 + 1], a, b[2], b[3]);
            }
        }

        CP_WAIT0();
        __syncthreads();
    }

    // Epilogue: bias + leaky_relu(0.01), register -> global
    const int g  = lid >> 2;
    const int c0 = (lid & 3) * 2;
    const int row0 = node0 + wid * 16 + g;
    const int row1 = row0 + 8;
#pragma unroll
    for (int nt = 0; nt < 8; ++nt) {
        int col = nt * 8 + c0;
        float bx = bias[col], by = bias[col + 1];
        float2 v0 = make_float2(acc[nt][0] + bx, acc[nt][1] + by);
        float2 v1 = make_float2(acc[nt][2] + bx, acc[nt][3] + by);
        v0.x = (v0.x > 0.0f) ? v0.x : 0.01f * v0.x;
        v0.y = (v0.y > 0.0f) ? v0.y : 0.01f * v0.y;
        v1.x = (v1.x > 0.0f) ? v1.x : 0.01f * v1.x;
        v1.y = (v1.y > 0.0f) ? v1.y : 0.01f * v1.y;
        if (row0 < N_NODES) *(float2*)(out + (size_t)row0 * F_OUT + col) = v0;
        if (row1 < N_NODES) *(float2*)(out + (size_t)row1 * F_OUT + col) = v1;
    }
}

// ---------------------------------------------------------------------------
// Harness entry. Inputs: h, pos, neighbor_idx, weight, bias_p
// ---------------------------------------------------------------------------
extern "C" void kernel_launch(void* const* d_in, const int* in_sizes, int n_in,
                              void* d_out, int out_size)
{
    const float* h    = (const float*)d_in[0];
    const float* pos  = (const float*)d_in[1];
    const int*   nidx = (const int*)d_in[2];
    const float* W    = (const float*)d_in[3];
    const float* bias = (const float*)d_in[4];
    float*       out  = (float*)d_out;

    static bool attr_set = false;
    if (!attr_set) {
        cudaFuncSetAttribute(gnn_mma_kernel,
                             cudaFuncAttributeMaxDynamicSharedMemorySize, SMEM_BYTES);
        attr_set = true;
    }

    convert_w_kernel<<<(K_NBR * F_IN * F_OUT + 255) / 256, 256>>>(W);
    gnn_mma_kernel<<<NBLK, 256, SMEM_BYTES>>>(h, nidx, pos, bias, out);
}

// round 10
// speedup vs baseline: 5.3355x; 1.6270x over previous
#include <cuda_runtime.h>
#include <cuda_fp16.h>
#include <cstdint>

// ---------------------------------------------------------------------------
// Problem constants
// ---------------------------------------------------------------------------
constexpr int N_NODES = 50000;
constexpr int K_NBR   = 32;
constexpr int F_IN    = 64;
constexpr int F_OUT   = 64;
constexpr int BM      = 128;                       // nodes per CTA tile
constexpr int NBLK    = (N_NODES + BM - 1) / BM;   // 391

// Padded row stride: 72 fp16 = 144 B -> conflict-free ldmatrix & STS.128.
constexpr int RS   = 72;
constexpr int RSB  = RS * 2;              // 144 B
constexpr int A_TILE = BM * RSB;          // 18432 B
constexpr int B_TILE = F_IN * RSB;        //  9216 B
constexpr int BUFSZ  = A_TILE + B_TILE;   // 27648 B
constexpr int INV_OFF    = 2 * BUFSZ;     // 55296
constexpr int INV_STRIDE = 33;            // pad -> bank (r+k)%32, conflict-free
constexpr int SMEM_BYTES = INV_OFF + BM * INV_STRIDE * 4;   // 72192 B

// ---------------------------------------------------------------------------
// Device scratch: fp16 W^T tiles and fp16 copy of h
// ---------------------------------------------------------------------------
__device__ uint4 g_Wh4[K_NBR * (B_TILE / 16)];
__device__ uint4 g_Hh4[(size_t)N_NODES * F_IN * 2 / 16];   // 6.4 MB

// ---------------------------------------------------------------------------
// PTX helpers (baseline PTX — valid at virtual target sm_103)
// ---------------------------------------------------------------------------
__device__ __forceinline__ uint32_t smem_u32(const void* p) {
    uint32_t a;
    asm("{ .reg .u64 t; cvta.to.shared.u64 t, %1; cvt.u32.u64 %0, t; }"
        : "=r"(a) : "l"(p));
    return a;
}
#define LDM_X4(r, addr) \
    asm volatile("ldmatrix.sync.aligned.m8n8.x4.shared.b16 {%0,%1,%2,%3}, [%4];" \
        : "=r"((r)[0]), "=r"((r)[1]), "=r"((r)[2]), "=r"((r)[3]) : "r"(addr))
#define LDM_X4T(r, addr) \
    asm volatile("ldmatrix.sync.aligned.m8n8.x4.trans.shared.b16 {%0,%1,%2,%3}, [%4];" \
        : "=r"((r)[0]), "=r"((r)[1]), "=r"((r)[2]), "=r"((r)[3]) : "r"(addr))
#define MMA16816(d, a, b0, b1) \
    asm volatile("mma.sync.aligned.m16n8k16.row.col.f32.f16.f16.f32 " \
        "{%0,%1,%2,%3}, {%4,%5,%6,%7}, {%8,%9}, {%0,%1,%2,%3};" \
        : "+f"((d)[0]), "+f"((d)[1]), "+f"((d)[2]), "+f"((d)[3]) \
        : "r"((a)[0]), "r"((a)[1]), "r"((a)[2]), "r"((a)[3]), "r"(b0), "r"(b1))
#define CP_ASYNC16(dst, src) \
    asm volatile("cp.async.cg.shared.global [%0], [%1], 16;" \
        :: "r"(dst), "l"(src) : "memory")
#define CP_COMMIT()  asm volatile("cp.async.commit_group;" ::: "memory")
#define CP_WAIT0()   asm volatile("cp.async.wait_group 0;" ::: "memory")

// ---------------------------------------------------------------------------
// Kernel 1: W -> fp16, transposed [nbr][k][n], padded rows (pad stays zero).
// ---------------------------------------------------------------------------
__global__ __launch_bounds__(256) void convert_w_kernel(const float* __restrict__ W)
{
    int idx = blockIdx.x * blockDim.x + threadIdx.x;
    if (idx >= K_NBR * F_IN * F_OUT) return;
    int nbr = idx >> 12;
    int kk  = (idx >> 6) & 63;
    int n   = idx & 63;
    float w = W[((size_t)nbr * F_IN + kk) * F_OUT + n];
    ((__half*)g_Wh4)[((size_t)nbr * F_IN + kk) * RS + n] = __float2half_rn(w);
}

// ---------------------------------------------------------------------------
// Kernel 2: h -> fp16 (bulk, vectorized)
// ---------------------------------------------------------------------------
__global__ __launch_bounds__(256) void convert_h_kernel(const float* __restrict__ h)
{
    int i = blockIdx.x * blockDim.x + threadIdx.x;   // over N*F_IN/4 = 800000
    if (i >= N_NODES * F_IN / 4) return;
    float4 v = ((const float4*)h)[i];
    __half2 a = __floats2half2_rn(v.x, v.y);
    __half2 b = __floats2half2_rn(v.z, v.w);
    ((uint2*)g_Hh4)[i] = make_uint2(*(uint32_t*)&a, *(uint32_t*)&b);
}

// ---------------------------------------------------------------------------
// Kernel 3: fused gather-scale-GEMM. 256 threads = 8 warps, 32x32 warp tiles.
// Per-CTA prologue precomputes 1/dist into smem. Steady state pipelines:
// nbr index 2 iters ahead, h-row 1 iter ahead (regs), B via cp.async.
// ---------------------------------------------------------------------------
extern __shared__ uint8_t dynsmem[];

__global__ __launch_bounds__(256, 3) void gnn_mma_kernel(
    const int* __restrict__ nidx, const float* __restrict__ pos,
    const float* __restrict__ bias, float* __restrict__ out)
{
    const int tid = threadIdx.x;
    const int wid = tid >> 5;
    const int lid = tid & 31;
    const int node0 = blockIdx.x * BM;

    const uint32_t sbase = smem_u32(dynsmem);
    float* invS = (float*)(dynsmem + INV_OFF);

    // Staging roles: row r = tid>>1 (0..127), half hh = tid&1
    const int r  = tid >> 1;
    const int hh = tid & 1;
    const int grow = node0 + r;
    const bool ok = (grow < N_NODES);
    const int* nrow = nidx + (size_t)grow * K_NBR;

    // ---- prologue: 1/dist for k in [hh*16, hh*16+16) ----
    {
        float pix = 0.f, piy = 0.f, piz = 0.f;
        if (ok) {
            pix = pos[(size_t)grow * 3 + 0];
            piy = pos[(size_t)grow * 3 + 1];
            piz = pos[(size_t)grow * 3 + 2];
        }
#pragma unroll 4
        for (int kk = 0; kk < 16; ++kk) {
            int k = hh * 16 + kk;
            float inv = 0.0f;
            if (ok) {
                int nbr = nrow[k];
                float dx = pix - pos[(size_t)nbr * 3 + 0];
                float dy = piy - pos[(size_t)nbr * 3 + 1];
                float dz = piz - pos[(size_t)nbr * 3 + 2];
                float sq = fmaf(dx, dx, fmaf(dy, dy, dz * dz));
                inv = (sq == 0.0f) ? 2.0f : rsqrtf(sq);   // dist==0 -> 0.5
            }
            invS[r * INV_STRIDE + k] = inv;
        }
    }
    __syncthreads();

    // Staging helpers
    uint8_t* AdstBase = dynsmem + r * RSB + hh * 64;
    auto scale_sts = [&](const uint4* hv, int kn, int buf) {
        __half2 inv2 = __float2half2_rn(invS[r * INV_STRIDE + kn]);
        uint8_t* dst = AdstBase + buf * BUFSZ;
#pragma unroll
        for (int j = 0; j < 4; ++j) {
            uint4 v = hv[j];
            __half2* p = (__half2*)&v;
            p[0] = __hmul2(p[0], inv2);
            p[1] = __hmul2(p[1], inv2);
            p[2] = __hmul2(p[2], inv2);
            p[3] = __hmul2(p[3], inv2);
            *(uint4*)(dst + j * 16) = v;
        }
    };
    auto stageB = [&](int k, int buf) {
        const uint4* src = g_Wh4 + (size_t)k * (B_TILE / 16);
        uint32_t dst = sbase + buf * BUFSZ + A_TILE;
        CP_ASYNC16(dst + tid * 16,         (const void*)(src + tid));
        CP_ASYNC16(dst + (tid + 256) * 16, (const void*)(src + tid + 256));
        if (tid < B_TILE / 16 - 512)
            CP_ASYNC16(dst + (tid + 512) * 16, (const void*)(src + tid + 512));
        CP_COMMIT();
    };

    // ---- prologue: stage k=0 ----
    {
        int nbr0 = ok ? nrow[0] : 0;
        uint4 hv[4];
        const uint4* hs = g_Hh4 + (size_t)nbr0 * 8 + hh * 4;
#pragma unroll
        for (int j = 0; j < 4; ++j) hv[j] = hs[j];
        scale_sts(hv, 0, 0);
        stageB(0, 0);
    }
    int nbr_cur = ok ? nrow[1] : 0;   // neighbor for k=1 (used at top of k=0)
    CP_WAIT0();
    __syncthreads();

    // MMA addressing: warp tile 32 rows x 32 cols
    const uint32_t mrow = (wid >> 1) * 32;
    const uint32_t ncol = (wid & 1) * 32;
    const uint32_t lrow = (lid & 15);
    const uint32_t loff = (lid >> 4) * 16;
    const uint32_t aOff = (mrow + lrow) * RSB + loff;
    const uint32_t bOff = A_TILE + lrow * RSB + ncol * 2 + loff;

    float acc[2][4][4];
#pragma unroll
    for (int t = 0; t < 2; ++t)
#pragma unroll
        for (int i = 0; i < 4; ++i)
#pragma unroll
            for (int j = 0; j < 4; ++j) acc[t][i][j] = 0.0f;

    for (int k = 0; k < K_NBR; ++k) {
        const int buf = k & 1;
        const int kn  = k + 1;

        // prefetch A row (k+1) into regs; B (k+1) via cp.async; nbr (k+2)
        uint4 hvn[4];
        if (kn < K_NBR) {
            const uint4* hs = g_Hh4 + (size_t)nbr_cur * 8 + hh * 4;
#pragma unroll
            for (int j = 0; j < 4; ++j) hvn[j] = hs[j];
            stageB(kn, buf ^ 1);
        }
        int nbr_nx = (k + 2 < K_NBR && ok) ? nrow[k + 2] : 0;

        // MMA on buf (neighbor k)
        const uint32_t ab = sbase + buf * BUFSZ;
#pragma unroll
        for (int kc = 0; kc < 4; ++kc) {
            uint32_t a0[4], a1[4];
            LDM_X4(a0, ab + aOff + kc * 32);
            LDM_X4(a1, ab + aOff + 16 * RSB + kc * 32);
#pragma unroll
            for (int g2 = 0; g2 < 2; ++g2) {
                uint32_t b[4];
                LDM_X4T(b, ab + bOff + g2 * 32 + kc * 16 * RSB);
                MMA16816(acc[0][g2 * 2 + 0], a0, b[0], b[1]);
                MMA16816(acc[0][g2 * 2 + 1], a0, b[2], b[3]);
                MMA16816(acc[1][g2 * 2 + 0], a1, b[0], b[1]);
                MMA16816(acc[1][g2 * 2 + 1], a1, b[2], b[3]);
            }
        }

        if (kn < K_NBR) scale_sts(hvn, kn, buf ^ 1);
        nbr_cur = nbr_nx;

        CP_WAIT0();
        __syncthreads();
    }

    // ---- epilogue: bias + leaky_relu(0.01) ----
    const int g  = lid >> 2;
    const int c0 = (lid & 3) * 2;
#pragma unroll
    for (int t = 0; t < 2; ++t) {
        const int row0 = node0 + mrow + t * 16 + g;
        const int row1 = row0 + 8;
#pragma unroll
        for (int nt = 0; nt < 4; ++nt) {
            int col = ncol + nt * 8 + c0;
            float bx = bias[col], by = bias[col + 1];
            float2 v0 = make_float2(acc[t][nt][0] + bx, acc[t][nt][1] + by);
            float2 v1 = make_float2(acc[t][nt][2] + bx, acc[t][nt][3] + by);
            v0.x = (v0.x > 0.0f) ? v0.x : 0.01f * v0.x;
            v0.y = (v0.y > 0.0f) ? v0.y : 0.01f * v0.y;
            v1.x = (v1.x > 0.0f) ? v1.x : 0.01f * v1.x;
            v1.y = (v1.y > 0.0f) ? v1.y : 0.01f * v1.y;
            if (row0 < N_NODES) *(float2*)(out + (size_t)row0 * F_OUT + col) = v0;
            if (row1 < N_NODES) *(float2*)(out + (size_t)row1 * F_OUT + col) = v1;
        }
    }
}

// ---------------------------------------------------------------------------
// Harness entry. Inputs: h, pos, neighbor_idx, weight, bias_p
// ---------------------------------------------------------------------------
extern "C" void kernel_launch(void* const* d_in, const int* in_sizes, int n_in,
                              void* d_out, int out_size)
{
    const float* h    = (const float*)d_in[0];
    const float* pos  = (const float*)d_in[1];
    const int*   nidx = (const int*)d_in[2];
    const float* W    = (const float*)d_in[3];
    const float* bias = (const float*)d_in[4];
    float*       out  = (float*)d_out;

    static bool attr_set = false;
    if (!attr_set) {
        cudaFuncSetAttribute(gnn_mma_kernel,
                             cudaFuncAttributeMaxDynamicSharedMemorySize, SMEM_BYTES);
        attr_set = true;
    }

    convert_w_kernel<<<(K_NBR * F_IN * F_OUT + 255) / 256, 256>>>(W);
    convert_h_kernel<<<(N_NODES * F_IN / 4 + 255) / 256, 256>>>(h);
    gnn_mma_kernel<<<NBLK, 256, SMEM_BYTES>>>(nidx, pos, bias, out);
}